// round 7
// baseline (speedup 1.0000x reference)
#include <cuda_runtime.h>
#include <cuda_bf16.h>
#include <cuda_fp16.h>
#include <cstdint>

#define NN 100000
#define EE 1600000
#define FIN 32
#define HD 128
#define SCAN_B 98                    // ceil(NN/1024)
#define ZB ((NN + 255) / 256)        // zero-deg blocks
#define XB ((NN * 16 + 255) / 256)   // x-convert blocks

// ---------------- persistent device scratch (no allocs allowed) ----------------
__device__ int   g_deg[NN];
__device__ int   g_rowptr[NN + 1];
__device__ int   g_pos[NN];
__device__ int   g_col[EE];
__device__ int   g_bsum[SCAN_B];
__device__ int   g_is64;

// fp16 gather mirrors
__device__ unsigned g_xh [(size_t)NN * 16];  // x fp16 (32 halves/row)
__device__ unsigned g_hh [(size_t)NN * 64];  // current h fp16 (128 halves/row)

// packed bf16x2 (hi,lo) activations, [node][kp] with kp = col/2
__device__ unsigned g_xbh[(size_t)NN * 16], g_xbl[(size_t)NN * 16];   // x
__device__ unsigned g_a32h[(size_t)NN * 16], g_a32l[(size_t)NN * 16]; // agg of x
__device__ unsigned g_aggh[(size_t)NN * 64], g_aggl[(size_t)NN * 64]; // agg of h
__device__ unsigned g_ph [(size_t)NN * 64], g_pl [(size_t)NN * 64];   // proj
__device__ unsigned g_h0h[(size_t)NN * 64], g_h0l[(size_t)NN * 64];   // h0
__device__ unsigned g_h1h[(size_t)NN * 64], g_h1l[(size_t)NN * 64];   // h1

// fp32 fallback target for h if d_out only holds yhat
__device__ float g_hscr[(size_t)NN * HD];

// packed bf16x2 (hi,lo) weights, [kp][col], 128 cols
__device__ unsigned g_w0h[32 * 128],  g_w0l[32 * 128];   // layer0: Ktot=64
__device__ unsigned g_wph[16 * 128],  g_wpl[16 * 128];   // proj:   Ktot=32
__device__ unsigned g_w1h[128 * 128], g_w1l[128 * 128];  // layer1: Ktot=256
__device__ unsigned g_w2h[128 * 128], g_w2l[128 * 128];  // layer2: Ktot=256

// ---------------- bf16 helpers ----------------
__device__ __forceinline__ unsigned packbf(float lo, float hi) {
    unsigned d;
    asm("cvt.rn.bf16x2.f32 %0, %1, %2;" : "=r"(d) : "f"(hi), "f"(lo));
    return d;
}
__device__ __forceinline__ float ubf_lo(unsigned p) { return __uint_as_float(p << 16); }
__device__ __forceinline__ float ubf_hi(unsigned p) { return __uint_as_float(p & 0xFFFF0000u); }
// pack fp32 pair -> (hi, lo) bf16x2 pair
__device__ __forceinline__ void split2(float a, float b, unsigned& ph, unsigned& pl) {
    ph = packbf(a, b);
    pl = packbf(a - ubf_lo(ph), b - ubf_hi(ph));
}

__device__ __forceinline__ void mma16(float* c,
    unsigned a0, unsigned a1, unsigned a2, unsigned a3,
    unsigned b0, unsigned b1)
{
    asm volatile(
        "mma.sync.aligned.m16n8k16.row.col.f32.bf16.bf16.f32 "
        "{%0,%1,%2,%3}, {%4,%5,%6,%7}, {%8,%9}, {%0,%1,%2,%3};"
        : "+f"(c[0]), "+f"(c[1]), "+f"(c[2]), "+f"(c[3])
        : "r"(a0), "r"(a1), "r"(a2), "r"(a3), "r"(b0), "r"(b1));
}

__device__ __forceinline__ int edge_at(const void* ei, long long idx) {
    if (g_is64) return (int)((const long long*)ei)[idx];
    return ((const int*)ei)[idx];
}

// ---------------- merged prologue: zero deg + detect + wprep + xconv ----------
__global__ void k_prologue(const void* ei, const float* __restrict__ x,
    const float* Wl0, const float* Wr0, const float* Wproj,
    const float* Wl1, const float* Wr1, const float* Wl2, const float* Wr2)
{
    int b = blockIdx.x;
    int tid = threadIdx.x;
    if (b < ZB) {
        int i = b * 256 + tid;
        if (i < NN) g_deg[i] = 0;
        if (b == 0) {
            __shared__ int s_nz;
            if (tid == 0) s_nz = 0;
            __syncthreads();
            const int* p = (const int*)ei;
            for (int j = tid; j < 8192; j += 256)
                if (p[2 * j + 1] != 0) s_nz = 1;
            __syncthreads();
            if (tid == 0) g_is64 = (s_nz == 0) ? 1 : 0;
        }
        return;
    }
    b -= ZB;
    if (b < 256) {
        int which = b >> 6;
        const float *W1, *W2; int kin, Ktot; unsigned *oh, *ol;
        if (which == 0)      { W1 = Wl0;   W2 = Wr0;   kin = FIN; Ktot = 2 * FIN; oh = g_w0h; ol = g_w0l; }
        else if (which == 1) { W1 = Wproj; W2 = Wproj; kin = FIN; Ktot = FIN;     oh = g_wph; ol = g_wpl; }
        else if (which == 2) { W1 = Wl1;   W2 = Wr1;   kin = HD;  Ktot = 2 * HD;  oh = g_w1h; ol = g_w1l; }
        else                 { W1 = Wl2;   W2 = Wr2;   kin = HD;  Ktot = 2 * HD;  oh = g_w2h; ol = g_w2l; }
        int idx = (b & 63) * 256 + tid;
        int total = (Ktot / 2) * 128;
        if (idx >= total) return;
        int kp = idx >> 7, col = idx & 127;
        int k = 2 * kp;
        const float* W = (k < kin) ? W1 : W2;
        int kk = (k < kin) ? k : (k - kin);
        float v0 = W[(size_t)kk * HD + col];
        float v1 = W[(size_t)(kk + 1) * HD + col];
        unsigned hp, lp; split2(v0, v1, hp, lp);
        oh[idx] = hp; ol[idx] = lp;
        return;
    }
    b -= 256;
    {
        int i = b * 256 + tid;
        if (i >= NN * 16) return;
        float2 v = *(const float2*)(x + 2 * (size_t)i);
        __half2 h = __floats2half2_rn(v.x, v.y);
        g_xh[i] = *(unsigned*)&h;
        unsigned hp, lp; split2(v.x, v.y, hp, lp);
        g_xbh[i] = hp; g_xbl[i] = lp;
    }
}

// ---------------- CSR build ----------------
__global__ void k_count(const void* ei) {
    int e = blockIdx.x * blockDim.x + threadIdx.x;
    if (e >= EE) return;
    atomicAdd(&g_deg[edge_at(ei, (long long)EE + e)], 1);
}

__global__ void k_scan1() {
    __shared__ int wsum[32];
    int i = blockIdx.x * 1024 + threadIdx.x;
    int v = (i < NN) ? g_deg[i] : 0;
    int lane = threadIdx.x & 31, w = threadIdx.x >> 5;
#pragma unroll
    for (int o = 16; o; o >>= 1) v += __shfl_xor_sync(0xFFFFFFFFu, v, o);
    if (lane == 0) wsum[w] = v;
    __syncthreads();
    if (w == 0) {
        int s = wsum[lane];
#pragma unroll
        for (int o = 16; o; o >>= 1) s += __shfl_xor_sync(0xFFFFFFFFu, s, o);
        if (lane == 0) g_bsum[blockIdx.x] = s;
    }
}

__global__ void k_scan3() {
    __shared__ int wsum[32];
    __shared__ int s_off;
    int b = blockIdx.x, tid = threadIdx.x;
    int lane = tid & 31, w = tid >> 5;
    if (w == 0) {
        int s = 0;
        for (int i = lane; i < SCAN_B; i += 32)
            if (i < b) s += g_bsum[i];
#pragma unroll
        for (int o = 16; o; o >>= 1) s += __shfl_xor_sync(0xFFFFFFFFu, s, o);
        if (lane == 0) s_off = s;
    }
    int i = b * 1024 + tid;
    int v = (i < NN) ? g_deg[i] : 0;
    int x = v;
#pragma unroll
    for (int o = 1; o < 32; o <<= 1) {
        int t = __shfl_up_sync(0xFFFFFFFFu, x, o);
        if (lane >= o) x += t;
    }
    if (lane == 31) wsum[w] = x;
    __syncthreads();
    if (w == 0) {
        int s = wsum[lane];
#pragma unroll
        for (int o = 1; o < 32; o <<= 1) {
            int t = __shfl_up_sync(0xFFFFFFFFu, s, o);
            if (lane >= o) s += t;
        }
        wsum[lane] = s;
    }
    __syncthreads();
    int off = (w > 0) ? wsum[w - 1] : 0;
    int excl = x + off + s_off - v;
    if (i < NN) { g_rowptr[i] = excl; g_pos[i] = excl; }
    if (b == 0 && tid == 0) g_rowptr[NN] = EE;
}

__global__ void k_fill(const void* ei) {
    int e = blockIdx.x * blockDim.x + threadIdx.x;
    if (e >= EE) return;
    int s = edge_at(ei, e);
    int d = edge_at(ei, (long long)EE + e);
    int p = atomicAdd(&g_pos[d], 1);
    g_col[p] = s;
}

// ---------------- mean aggregation over fp16 mirrors, bf16 hi/lo output ------
// DIM=32: 16 lanes per node, each lane owns one half2 (cols 2l, 2l+1) -> kp=l
__global__ void k_agg32h() {
    int t = blockIdx.x * blockDim.x + threadIdx.x;
    int node = t >> 4;
    int l = t & 15;
    if (node >= NN) return;
    int beg = g_rowptr[node], end = g_rowptr[node + 1];
    float inv = 1.f / fmaxf((float)(end - beg), 1.f);
    float ax = 0.f, ay = 0.f;
    int e = beg;
    for (; e + 4 <= end; e += 4) {
        int s0 = g_col[e], s1 = g_col[e + 1], s2 = g_col[e + 2], s3 = g_col[e + 3];
        unsigned u0 = g_xh[(size_t)s0 * 16 + l];
        unsigned u1 = g_xh[(size_t)s1 * 16 + l];
        unsigned u2 = g_xh[(size_t)s2 * 16 + l];
        unsigned u3 = g_xh[(size_t)s3 * 16 + l];
        float2 f0 = __half22float2(*(__half2*)&u0);
        float2 f1 = __half22float2(*(__half2*)&u1);
        float2 f2 = __half22float2(*(__half2*)&u2);
        float2 f3 = __half22float2(*(__half2*)&u3);
        ax += f0.x + f1.x + f2.x + f3.x;
        ay += f0.y + f1.y + f2.y + f3.y;
    }
    for (; e < end; e++) {
        unsigned u = g_xh[(size_t)g_col[e] * 16 + l];
        float2 f = __half22float2(*(__half2*)&u);
        ax += f.x; ay += f.y;
    }
    unsigned hp, lp; split2(ax * inv, ay * inv, hp, lp);
    g_a32h[(size_t)node * 16 + l] = hp;
    g_a32l[(size_t)node * 16 + l] = lp;
}

// DIM=128: half-warp per node; lane l owns cols 8l..8l+7 (kps 4l..4l+3).
// Unroll 4 edges for MLP.
__global__ void k_agg128h() {
    int w = (blockIdx.x * blockDim.x + threadIdx.x) >> 5;
    int lane = threadIdx.x & 31;
    int half = lane >> 4;
    int l = lane & 15;
    int node = w * 2 + half;
    if (node >= NN) return;
    int beg = g_rowptr[node], end = g_rowptr[node + 1];
    float inv = 1.f / fmaxf((float)(end - beg), 1.f);
    float a0 = 0.f, a1 = 0.f, a2 = 0.f, a3 = 0.f;
    float a4 = 0.f, a5 = 0.f, a6 = 0.f, a7 = 0.f;
    const uint4* hh4 = (const uint4*)g_hh;
    int e = beg;
    for (; e + 4 <= end; e += 4) {
        int s0 = g_col[e], s1 = g_col[e + 1], s2 = g_col[e + 2], s3 = g_col[e + 3];
        uint4 u0 = hh4[(size_t)s0 * 16 + l];
        uint4 u1 = hh4[(size_t)s1 * 16 + l];
        uint4 u2 = hh4[(size_t)s2 * 16 + l];
        uint4 u3 = hh4[(size_t)s3 * 16 + l];
#define ACC4(U) { \
        float2 p0 = __half22float2(*(__half2*)&U.x); \
        float2 p1 = __half22float2(*(__half2*)&U.y); \
        float2 p2 = __half22float2(*(__half2*)&U.z); \
        float2 p3 = __half22float2(*(__half2*)&U.w); \
        a0 += p0.x; a1 += p0.y; a2 += p1.x; a3 += p1.y; \
        a4 += p2.x; a5 += p2.y; a6 += p3.x; a7 += p3.y; }
        ACC4(u0) ACC4(u1) ACC4(u2) ACC4(u3)
    }
    for (; e < end; e++) {
        uint4 u = hh4[(size_t)g_col[e] * 16 + l];
        ACC4(u)
    }
#undef ACC4
    unsigned h0, l0, h1, l1, h2, l2, h3, l3;
    split2(a0 * inv, a1 * inv, h0, l0);
    split2(a2 * inv, a3 * inv, h1, l1);
    split2(a4 * inv, a5 * inv, h2, l2);
    split2(a6 * inv, a7 * inv, h3, l3);
    *(uint4*)(g_aggh + (size_t)node * 64 + 4 * l) = make_uint4(h0, h1, h2, h3);
    *(uint4*)(g_aggl + (size_t)node * 64 + 4 * l) = make_uint4(l0, l1, l2, l3);
}

// ---------------- fused bf16x3 GEMM (+bias) [+ LN+ReLU+res [+ head]] ---------
// A operands pre-packed bf16 hi/lo, [node][kp]. MODE 0: packed raw write (proj).
// MODE 1: relu(LN(.))+res -> packed bf16 + fp16 mirror. MODE 2: MODE1 -> fp32 out + head.
template <int MODE>
__global__ __launch_bounds__(256, 2) void k_mma_gemm(
    const unsigned* __restrict__ A1h, const unsigned* __restrict__ A1l,
    const unsigned* __restrict__ A2h, const unsigned* __restrict__ A2l,
    int kinp, int Ktotp,
    const unsigned* __restrict__ Wph, const unsigned* __restrict__ Wpl,
    const float* __restrict__ bias,
    const float* __restrict__ gamma, const float* __restrict__ beta,
    const unsigned* __restrict__ resh, const unsigned* __restrict__ resl,
    unsigned* __restrict__ outh, unsigned* __restrict__ outl,
    unsigned* __restrict__ hh,
    float* __restrict__ out,
    const float* __restrict__ Wh, const float* __restrict__ bh,
    float* __restrict__ y)
{
    __shared__ unsigned sAh[8][132], sAl[8][132];
    __shared__ unsigned sWh[8][132], sWl[8][132];
    __shared__ float s_sum[4][128], s_sq[4][128];
    __shared__ float s_mu[128], s_rstd[128], s_y[128];

    const int tid = threadIdx.x;
    const int lane = tid & 31, wid = tid >> 5;
    const int wm = wid >> 2, wn = wid & 3;
    const int g = lane >> 2, tig = lane & 3;
    const int node0 = blockIdx.x * 128;

    float acc[4][4][4];
#pragma unroll
    for (int mt = 0; mt < 4; mt++)
#pragma unroll
        for (int nt = 0; nt < 4; nt++)
#pragma unroll
            for (int i = 0; i < 4; i++) acc[mt][nt][i] = 0.f;

    const int arow = tid >> 1;            // 0..127
    const int aq   = (tid & 1) * 4;       // kp quad offset
    const int wrow = tid >> 5;
    const int wcol = (tid & 31) * 4;
    const int anode = node0 + arow;

    for (int c = 0; c < Ktotp; c += 8) {
        const unsigned *Sh, *Sl; int kpo, stride;
        if (c < kinp) { Sh = A1h; Sl = A1l; kpo = c; stride = kinp; }
        else          { Sh = A2h; Sl = A2l; kpo = c - kinp; stride = Ktotp - kinp; }

        uint4 vh = make_uint4(0, 0, 0, 0), vl = make_uint4(0, 0, 0, 0);
        if (anode < NN) {
            vh = *(const uint4*)(Sh + (size_t)anode * stride + kpo + aq);
            vl = *(const uint4*)(Sl + (size_t)anode * stride + kpo + aq);
        }
        sAh[aq + 0][arow] = vh.x; sAh[aq + 1][arow] = vh.y;
        sAh[aq + 2][arow] = vh.z; sAh[aq + 3][arow] = vh.w;
        sAl[aq + 0][arow] = vl.x; sAl[aq + 1][arow] = vl.y;
        sAl[aq + 2][arow] = vl.z; sAl[aq + 3][arow] = vl.w;

        *(uint4*)&sWh[wrow][wcol] = *(const uint4*)(Wph + (size_t)(c + wrow) * 128 + wcol);
        *(uint4*)&sWl[wrow][wcol] = *(const uint4*)(Wpl + (size_t)(c + wrow) * 128 + wcol);
        __syncthreads();

        unsigned bh0[4], bh1[4], bl0[4], bl1[4];
#pragma unroll
        for (int nt = 0; nt < 4; nt++) {
            int n = wn * 32 + nt * 8 + g;
            bh0[nt] = sWh[tig][n];     bh1[nt] = sWh[tig + 4][n];
            bl0[nt] = sWl[tig][n];     bl1[nt] = sWl[tig + 4][n];
        }
#pragma unroll
        for (int mt = 0; mt < 4; mt++) {
            int r = wm * 64 + mt * 16 + g;
            unsigned a0h = sAh[tig][r],     a1h = sAh[tig][r + 8];
            unsigned a2h = sAh[tig + 4][r], a3h = sAh[tig + 4][r + 8];
            unsigned a0l = sAl[tig][r],     a1l = sAl[tig][r + 8];
            unsigned a2l = sAl[tig + 4][r], a3l = sAl[tig + 4][r + 8];
#pragma unroll
            for (int nt = 0; nt < 4; nt++) {
                mma16(acc[mt][nt], a0h, a1h, a2h, a3h, bh0[nt], bh1[nt]);
                mma16(acc[mt][nt], a0h, a1h, a2h, a3h, bl0[nt], bl1[nt]);
                mma16(acc[mt][nt], a0l, a1l, a2l, a3l, bh0[nt], bh1[nt]);
            }
        }
        __syncthreads();
    }

    if (MODE == 0) {
        // packed raw write (proj, no bias)
#pragma unroll
        for (int mt = 0; mt < 4; mt++) {
            int r0 = wm * 64 + mt * 16 + g;
            int n0 = node0 + r0, n1 = n0 + 8;
#pragma unroll
            for (int nt = 0; nt < 4; nt++) {
                int kp = (wn * 32 + nt * 8 + tig * 2) >> 1;
                if (n0 < NN) {
                    unsigned hp, lp; split2(acc[mt][nt][0], acc[mt][nt][1], hp, lp);
                    outh[(size_t)n0 * 64 + kp] = hp;
                    outl[(size_t)n0 * 64 + kp] = lp;
                }
                if (n1 < NN) {
                    unsigned hp, lp; split2(acc[mt][nt][2], acc[mt][nt][3], hp, lp);
                    outh[(size_t)n1 * 64 + kp] = hp;
                    outl[(size_t)n1 * 64 + kp] = lp;
                }
            }
        }
        return;
    }

    // ---- bias add (pre-LN) ----
#pragma unroll
    for (int mt = 0; mt < 4; mt++)
#pragma unroll
        for (int nt = 0; nt < 4; nt++) {
            int c0 = wn * 32 + nt * 8 + tig * 2;
            float2 b2 = *(const float2*)(bias + c0);
            acc[mt][nt][0] += b2.x; acc[mt][nt][1] += b2.y;
            acc[mt][nt][2] += b2.x; acc[mt][nt][3] += b2.y;
        }

    // ---- LN stats ----
#pragma unroll
    for (int mt = 0; mt < 4; mt++) {
        float s0 = 0.f, q0 = 0.f, s1 = 0.f, q1 = 0.f;
#pragma unroll
        for (int nt = 0; nt < 4; nt++) {
            float a0 = acc[mt][nt][0], a1 = acc[mt][nt][1];
            float a2 = acc[mt][nt][2], a3 = acc[mt][nt][3];
            s0 += a0 + a1; q0 += a0 * a0 + a1 * a1;
            s1 += a2 + a3; q1 += a2 * a2 + a3 * a3;
        }
#pragma unroll
        for (int o = 1; o < 4; o <<= 1) {
            s0 += __shfl_xor_sync(0xFFFFFFFFu, s0, o);
            q0 += __shfl_xor_sync(0xFFFFFFFFu, q0, o);
            s1 += __shfl_xor_sync(0xFFFFFFFFu, s1, o);
            q1 += __shfl_xor_sync(0xFFFFFFFFu, q1, o);
        }
        if (tig == 0) {
            int r0 = wm * 64 + mt * 16 + g;
            s_sum[wn][r0] = s0;     s_sq[wn][r0] = q0;
            s_sum[wn][r0 + 8] = s1; s_sq[wn][r0 + 8] = q1;
        }
    }
    __syncthreads();
    if (tid < 128) {
        float s = s_sum[0][tid] + s_sum[1][tid] + s_sum[2][tid] + s_sum[3][tid];
        float q = s_sq[0][tid] + s_sq[1][tid] + s_sq[2][tid] + s_sq[3][tid];
        float mu = s * (1.f / 128.f);
        float var = q * (1.f / 128.f) - mu * mu;
        s_mu[tid] = mu;
        s_rstd[tid] = rsqrtf(var + 1e-5f);
        if (MODE == 2) s_y[tid] = 0.f;
    }
    __syncthreads();

    // ---- apply LN + relu + residual (+ head) ----
#pragma unroll
    for (int mt = 0; mt < 4; mt++) {
        int r0 = wm * 64 + mt * 16 + g, r1 = r0 + 8;
        int n0 = node0 + r0, n1 = node0 + r1;
        float mu0 = s_mu[r0], rs0 = s_rstd[r0];
        float mu1 = s_mu[r1], rs1 = s_rstd[r1];
        float y0 = 0.f, y1 = 0.f;
#pragma unroll
        for (int nt = 0; nt < 4; nt++) {
            int c0 = wn * 32 + nt * 8 + tig * 2;
            int kp = c0 >> 1;
            float2 g2 = *(const float2*)(gamma + c0);
            float2 b2 = *(const float2*)(beta + c0);
            float v00 = fmaxf((acc[mt][nt][0] - mu0) * rs0 * g2.x + b2.x, 0.f);
            float v01 = fmaxf((acc[mt][nt][1] - mu0) * rs0 * g2.y + b2.y, 0.f);
            float v10 = fmaxf((acc[mt][nt][2] - mu1) * rs1 * g2.x + b2.x, 0.f);
            float v11 = fmaxf((acc[mt][nt][3] - mu1) * rs1 * g2.y + b2.y, 0.f);
            if (n0 < NN) {
                unsigned rh = resh[(size_t)n0 * 64 + kp], rl = resl[(size_t)n0 * 64 + kp];
                v00 += ubf_lo(rh) + ubf_lo(rl);
                v01 += ubf_hi(rh) + ubf_hi(rl);
                if (MODE == 1) {
                    unsigned hp, lp; split2(v00, v01, hp, lp);
                    outh[(size_t)n0 * 64 + kp] = hp;
                    outl[(size_t)n0 * 64 + kp] = lp;
                    __half2 hv = __floats2half2_rn(v00, v01);
                    hh[(size_t)n0 * 64 + kp] = *(unsigned*)&hv;
                } else {
                    *(float2*)(out + (size_t)n0 * HD + c0) = make_float2(v00, v01);
                }
            }
            if (n1 < NN) {
                unsigned rh = resh[(size_t)n1 * 64 + kp], rl = resl[(size_t)n1 * 64 + kp];
                v10 += ubf_lo(rh) + ubf_lo(rl);
                v11 += ubf_hi(rh) + ubf_hi(rl);
                if (MODE == 1) {
                    unsigned hp, lp; split2(v10, v11, hp, lp);
                    outh[(size_t)n1 * 64 + kp] = hp;
                    outl[(size_t)n1 * 64 + kp] = lp;
                    __half2 hv = __floats2half2_rn(v10, v11);
                    hh[(size_t)n1 * 64 + kp] = *(unsigned*)&hv;
                } else {
                    *(float2*)(out + (size_t)n1 * HD + c0) = make_float2(v10, v11);
                }
            }
            if (MODE == 2) {
                float2 w2 = *(const float2*)(Wh + c0);
                y0 += v00 * w2.x + v01 * w2.y;
                y1 += v10 * w2.x + v11 * w2.y;
            }
        }
        if (MODE == 2) {
#pragma unroll
            for (int o = 1; o < 4; o <<= 1) {
                y0 += __shfl_xor_sync(0xFFFFFFFFu, y0, o);
                y1 += __shfl_xor_sync(0xFFFFFFFFu, y1, o);
            }
            if (tig == 0) {
                atomicAdd(&s_y[r0], y0);
                atomicAdd(&s_y[r1], y1);
            }
        }
    }
    if (MODE == 2) {
        __syncthreads();
        if (tid < 128 && node0 + tid < NN)
            y[node0 + tid] = s_y[tid] + bh[0];
    }
}

// ---------------- launcher ----------------
extern "C" void kernel_launch(void* const* d_in, const int* in_sizes, int n_in,
                              void* d_out, int out_size)
{
    const float* x     = (const float*)d_in[0];
    const void*  ei    = d_in[1];
    const float* Wl0   = (const float*)d_in[2];
    const float* bl0   = (const float*)d_in[3];
    const float* Wr0   = (const float*)d_in[4];
    const float* g0    = (const float*)d_in[5];
    const float* be0   = (const float*)d_in[6];
    const float* Wl1   = (const float*)d_in[7];
    const float* bl1   = (const float*)d_in[8];
    const float* Wr1   = (const float*)d_in[9];
    const float* g1    = (const float*)d_in[10];
    const float* be1   = (const float*)d_in[11];
    const float* Wl2   = (const float*)d_in[12];
    const float* bl2   = (const float*)d_in[13];
    const float* Wr2   = (const float*)d_in[14];
    const float* g2    = (const float*)d_in[15];
    const float* be2   = (const float*)d_in[16];
    const float* Wproj = (const float*)d_in[17];
    const float* Wh    = (const float*)d_in[18];
    const float* bh    = (const float*)d_in[19];

    float* out = (float*)d_out;

    unsigned *xbh, *xbl, *a32h, *a32l, *aggh, *aggl, *ph, *pl;
    unsigned *h0h, *h0l, *h1h, *h1l, *hh;
    float* hscr;
    cudaGetSymbolAddress((void**)&xbh,  g_xbh);  cudaGetSymbolAddress((void**)&xbl,  g_xbl);
    cudaGetSymbolAddress((void**)&a32h, g_a32h); cudaGetSymbolAddress((void**)&a32l, g_a32l);
    cudaGetSymbolAddress((void**)&aggh, g_aggh); cudaGetSymbolAddress((void**)&aggl, g_aggl);
    cudaGetSymbolAddress((void**)&ph,   g_ph);   cudaGetSymbolAddress((void**)&pl,   g_pl);
    cudaGetSymbolAddress((void**)&h0h,  g_h0h);  cudaGetSymbolAddress((void**)&h0l,  g_h0l);
    cudaGetSymbolAddress((void**)&h1h,  g_h1h);  cudaGetSymbolAddress((void**)&h1l,  g_h1l);
    cudaGetSymbolAddress((void**)&hh,   g_hh);
    cudaGetSymbolAddress((void**)&hscr, g_hscr);
    unsigned *w0h, *w0l, *wph, *wpl, *w1h, *w1l, *w2h, *w2l;
    cudaGetSymbolAddress((void**)&w0h, g_w0h); cudaGetSymbolAddress((void**)&w0l, g_w0l);
    cudaGetSymbolAddress((void**)&wph, g_wph); cudaGetSymbolAddress((void**)&wpl, g_wpl);
    cudaGetSymbolAddress((void**)&w1h, g_w1h); cudaGetSymbolAddress((void**)&w1l, g_w1l);
    cudaGetSymbolAddress((void**)&w2h, g_w2h); cudaGetSymbolAddress((void**)&w2l, g_w2l);

    float* hout = (out_size >= NN + NN * HD) ? (out + NN) : hscr;

    const int TB = 256;
    dim3 gE((EE + TB - 1) / TB);
    dim3 gGemm((NN + 127) / 128);
    dim3 gAgg32((NN * 16 + TB - 1) / TB);
    dim3 gAgg128((NN / 2 + 7) / 8);
    dim3 gPro(ZB + 256 + XB);

    k_prologue<<<gPro, TB>>>(ei, x, Wl0, Wr0, Wproj, Wl1, Wr1, Wl2, Wr2);
    k_count<<<gE, TB>>>(ei);
    k_scan1<<<SCAN_B, 1024>>>();
    k_scan3<<<SCAN_B, 1024>>>();
    k_fill<<<gE, TB>>>(ei);

    // ---- layer 0 ----
    k_agg32h<<<gAgg32, TB>>>();
    k_mma_gemm<0><<<gGemm, TB>>>(xbh, xbl, xbh, xbl, 16, 16, wph, wpl,
                                 nullptr, nullptr, nullptr, nullptr, nullptr,
                                 ph, pl, nullptr, nullptr, nullptr, nullptr, nullptr);
    k_mma_gemm<1><<<gGemm, TB>>>(a32h, a32l, xbh, xbl, 16, 32, w0h, w0l,
                                 bl0, g0, be0, ph, pl,
                                 h0h, h0l, hh, nullptr, nullptr, nullptr, nullptr);

    // ---- layer 1 ----
    k_agg128h<<<gAgg128, TB>>>();
    k_mma_gemm<1><<<gGemm, TB>>>(aggh, aggl, h0h, h0l, 64, 128, w1h, w1l,
                                 bl1, g1, be1, h0h, h0l,
                                 h1h, h1l, hh, nullptr, nullptr, nullptr, nullptr);

    // ---- layer 2 (+ fused head) ----
    k_agg128h<<<gAgg128, TB>>>();
    k_mma_gemm<2><<<gGemm, TB>>>(aggh, aggl, h1h, h1l, 64, 128, w2h, w2l,
                                 bl2, g2, be2, h1h, h1l,
                                 nullptr, nullptr, nullptr, hout, Wh, bh, out);
}